// round 10
// baseline (speedup 1.0000x reference)
#include <cuda_runtime.h>

#define D 128
#define MAXN 40000
#define MAXE 640000

#define CNT_SHIFT 52
#define FIX_MASK  ((1ull << 52) - 1ull)
#define FIX_SCALE 1099511627776.0f            // 2^40
#define FIX_INV   (1.0f / 1099511627776.0f)

// ---------------- scratch (static device globals; no allocation) -------------
__device__ unsigned long long g_acc[MAXN];    // cnt[63:52] | fixpoint sum(ea)[51:0]
__device__ float g_dinv[MAXN];
__device__ int   g_offs[MAXN + 1];
__device__ int   g_cursor[MAXN];
__device__ __align__(16) int2  g_edge[MAXE];  // {src, nrm as float bits}
__device__ __align__(16) float g_H[MAXN * D];
__device__ __align__(16) float g_G[MAXN * D];
__device__ int   g_is64;

// ---------------- f32x2 packed-FMA helpers ------------------------------------
__device__ __forceinline__ unsigned long long pack2(float lo, float hi) {
    unsigned long long d;
    asm("mov.b64 %0, {%1, %2};" : "=l"(d) : "f"(lo), "f"(hi));
    return d;
}
__device__ __forceinline__ void unpack2(unsigned long long v, float& lo, float& hi) {
    asm("mov.b64 {%0, %1}, %2;" : "=f"(lo), "=f"(hi) : "l"(v));
}
__device__ __forceinline__ unsigned long long fma2(unsigned long long a,
                                                   unsigned long long b,
                                                   unsigned long long c) {
    unsigned long long d;
    asm("fma.rn.f32x2 %0, %1, %2, %3;" : "=l"(d) : "l"(a), "l"(b), "l"(c));
    return d;
}

// ---------------- init + dtype probe ------------------------------------------
__global__ void k_init(const void* __restrict__ ei, int n) {
    int i = blockIdx.x * blockDim.x + threadIdx.x;
    if (i < n) g_acc[i] = 0ull;
    if (blockIdx.x == 0) {
        const long long* p = (const long long*)ei;
        bool bad = false;
        for (int j = threadIdx.x; j < 1024; j += blockDim.x) {
            long long v = p[j];
            if (v < 0 || v >= MAXN) bad = true;
        }
        bad = __syncthreads_or(bad);
        if (threadIdx.x == 0) g_is64 = bad ? 0 : 1;
    }
}

__device__ __forceinline__ int edge_at(const void* ei, long long idx) {
    if (g_is64) return (int)((const long long*)ei)[idx];
    return ((const int*)ei)[idx];
}

// one 64-bit atomic per edge: +1 count, +ea in 2^-40 fixed point
__global__ void k_deg(const void* __restrict__ ei,
                      const float* __restrict__ ea, int e) {
    int i = blockIdx.x * blockDim.x + threadIdx.x;
    if (i < e) {
        int dst = edge_at(ei, (long long)e + i);
        unsigned long long fx =
            (unsigned long long)__float2ll_rn(ea[i] * FIX_SCALE);
        atomicAdd(&g_acc[dst], (1ull << CNT_SHIFT) | fx);
    }
}

// Single-block scan of counts -> offs/cursor; also emits dinv = rsqrt(deg).
__global__ void k_scan(int n) {
    __shared__ int s[1024];
    int t = threadIdx.x;
    int ch = (n + 1023) >> 10;
    int base = t * ch;
    int sum = 0;
    for (int j = 0; j < ch; j++) {
        int idx = base + j;
        if (idx < n) {
            unsigned long long v = g_acc[idx];
            int c = (int)(v >> CNT_SHIFT);
            float deg = 1.0f + (float)(v & FIX_MASK) * FIX_INV;
            g_dinv[idx] = rsqrtf(deg);
            sum += c;
        }
    }
    s[t] = sum;
    __syncthreads();
    for (int off = 1; off < 1024; off <<= 1) {
        int v = (t >= off) ? s[t - off] : 0;
        __syncthreads();
        s[t] += v;
        __syncthreads();
    }
    if (t == 1023) g_offs[n] = s[1023];
    int prefix = (t == 0) ? 0 : s[t - 1];
    for (int j = 0; j < ch; j++) {
        int idx = base + j;
        if (idx < n) {
            g_offs[idx]   = prefix;
            g_cursor[idx] = prefix;
            prefix += (int)(g_acc[idx] >> CNT_SHIFT);
        }
    }
}

__global__ void k_fill(const void* __restrict__ ei,
                       const float* __restrict__ ea, int e) {
    int i = blockIdx.x * blockDim.x + threadIdx.x;
    if (i < e) {
        int src = edge_at(ei, i);
        int dst = edge_at(ei, (long long)e + i);
        float nrm = g_dinv[src] * ea[i] * g_dinv[dst];
        int pos = atomicAdd(&g_cursor[dst], 1);
        g_edge[pos] = make_int2(src, __float_as_int(nrm));
    }
}

// ---------------- SGEMM (f32x2): g_H[n,128] = A[n,128] @ W[128,128] ----------
// 256 threads, 128x128 tile, BK=16. Thread = 8 rows x 8 cols; rows packed in
// pairs -> fma.rn.f32x2. X tile k-major (stride 130).  [R8 proven version]
template <int USE_G>
__global__ void __launch_bounds__(256) k_gemm(const float* __restrict__ Ain,
                                              const float* __restrict__ W,
                                              int nrows) {
    const float* __restrict__ A = USE_G ? (const float*)g_G : Ain;
    __shared__ float xs_t[16][130];
    __shared__ float ws[16][128];
    int tid = threadIdx.x;
    int tx = tid & 15;
    int ty = tid >> 4;
    int row0 = blockIdx.x * 128;

    int lrow = tid >> 1;
    int lseg = (tid & 1) * 8;
    int grow = row0 + lrow;
    if (grow >= nrows) grow = nrows - 1;

    unsigned long long acc[4][8];
#pragma unroll
    for (int m = 0; m < 4; m++)
#pragma unroll
        for (int nn = 0; nn < 8; nn++) acc[m][nn] = 0ull;

    for (int k0 = 0; k0 < D; k0 += 16) {
        float4 va = *(const float4*)&A[grow * D + k0 + lseg];
        float4 vb = *(const float4*)&A[grow * D + k0 + lseg + 4];
        xs_t[lseg + 0][lrow] = va.x; xs_t[lseg + 1][lrow] = va.y;
        xs_t[lseg + 2][lrow] = va.z; xs_t[lseg + 3][lrow] = va.w;
        xs_t[lseg + 4][lrow] = vb.x; xs_t[lseg + 5][lrow] = vb.y;
        xs_t[lseg + 6][lrow] = vb.z; xs_t[lseg + 7][lrow] = vb.w;
#pragma unroll
        for (int j = 0; j < 2; j++) {
            int i = tid + j * 256;
            int r = i >> 5;
            int c4 = (i & 31) * 4;
            *(float4*)&ws[r][c4] = *(const float4*)&W[(k0 + r) * D + c4];
        }
        __syncthreads();

#pragma unroll
        for (int kk = 0; kk < 16; kk++) {
            unsigned long long rm2[4];
#pragma unroll
            for (int m = 0; m < 4; m++)
                rm2[m] = *(const unsigned long long*)&xs_t[kk][ty * 8 + 2 * m];
            float4 fa = *(const float4*)&ws[kk][tx * 8];
            float4 fb = *(const float4*)&ws[kk][tx * 8 + 4];
            unsigned long long rnb[8];
            rnb[0] = pack2(fa.x, fa.x); rnb[1] = pack2(fa.y, fa.y);
            rnb[2] = pack2(fa.z, fa.z); rnb[3] = pack2(fa.w, fa.w);
            rnb[4] = pack2(fb.x, fb.x); rnb[5] = pack2(fb.y, fb.y);
            rnb[6] = pack2(fb.z, fb.z); rnb[7] = pack2(fb.w, fb.w);
#pragma unroll
            for (int m = 0; m < 4; m++)
#pragma unroll
                for (int nn = 0; nn < 8; nn++)
                    acc[m][nn] = fma2(rm2[m], rnb[nn], acc[m][nn]);
        }
        __syncthreads();
    }

#pragma unroll
    for (int m = 0; m < 4; m++) {
        float lo[8], hi[8];
#pragma unroll
        for (int nn = 0; nn < 8; nn++) unpack2(acc[m][nn], lo[nn], hi[nn]);
        int r_lo = row0 + ty * 8 + 2 * m;
        int r_hi = r_lo + 1;
        int c = tx * 8;
        if (r_lo < nrows) {
            *(float4*)&g_H[r_lo * D + c]     = make_float4(lo[0], lo[1], lo[2], lo[3]);
            *(float4*)&g_H[r_lo * D + c + 4] = make_float4(lo[4], lo[5], lo[6], lo[7]);
        }
        if (r_hi < nrows) {
            *(float4*)&g_H[r_hi * D + c]     = make_float4(hi[0], hi[1], hi[2], hi[3]);
            *(float4*)&g_H[r_hi * D + c + 4] = make_float4(hi[4], hi[5], hi[6], hi[7]);
        }
    }
}

// ---------------- aggregation: warp per node, float4 per lane ----------------
template <int LN>
__global__ void k_agg(const float* __restrict__ bias,
                      const float* __restrict__ gamma, const float* __restrict__ beta,
                      float* __restrict__ outp, int n) {
    int w = (blockIdx.x * blockDim.x + threadIdx.x) >> 5;
    int lane = threadIdx.x & 31;
    if (w >= n) return;

    const float4* __restrict__ H4 = (const float4*)g_H;
    float di = g_dinv[w];
    float selfw = di * di;
    float4 h = __ldg(&H4[w * 32 + lane]);
    float4 acc = make_float4(h.x * selfw, h.y * selfw, h.z * selfw, h.w * selfw);

    int ib = g_offs[w];
    int ie = g_offs[w + 1];
    int i = ib;
    for (; i + 4 <= ie; i += 4) {
        int2 e0 = g_edge[i],     e1 = g_edge[i + 1];
        int2 e2 = g_edge[i + 2], e3 = g_edge[i + 3];
        float w0 = __int_as_float(e0.y), w1 = __int_as_float(e1.y);
        float w2 = __int_as_float(e2.y), w3 = __int_as_float(e3.y);
        float4 a = __ldg(&H4[e0.x * 32 + lane]);
        float4 b = __ldg(&H4[e1.x * 32 + lane]);
        float4 c = __ldg(&H4[e2.x * 32 + lane]);
        float4 d = __ldg(&H4[e3.x * 32 + lane]);
        acc.x += a.x * w0; acc.y += a.y * w0; acc.z += a.z * w0; acc.w += a.w * w0;
        acc.x += b.x * w1; acc.y += b.y * w1; acc.z += b.z * w1; acc.w += b.w * w1;
        acc.x += c.x * w2; acc.y += c.y * w2; acc.z += c.z * w2; acc.w += c.w * w2;
        acc.x += d.x * w3; acc.y += d.y * w3; acc.z += d.z * w3; acc.w += d.w * w3;
    }
    for (; i < ie; i++) {
        int2 e0 = g_edge[i];
        float w0 = __int_as_float(e0.y);
        float4 a = __ldg(&H4[e0.x * 32 + lane]);
        acc.x += a.x * w0; acc.y += a.y * w0; acc.z += a.z * w0; acc.w += a.w * w0;
    }

    float4 b4 = ((const float4*)bias)[lane];
    acc.x = fmaxf(acc.x + b4.x, 0.0f);
    acc.y = fmaxf(acc.y + b4.y, 0.0f);
    acc.z = fmaxf(acc.z + b4.z, 0.0f);
    acc.w = fmaxf(acc.w + b4.w, 0.0f);

    if (LN) {
        float s1 = acc.x + acc.y + acc.z + acc.w;
#pragma unroll
        for (int o = 16; o > 0; o >>= 1)
            s1 += __shfl_xor_sync(0xffffffffu, s1, o);
        float mu = s1 * (1.0f / 128.0f);
        float dx = acc.x - mu, dy = acc.y - mu, dz = acc.z - mu, dw = acc.w - mu;
        float s2 = dx * dx + dy * dy + dz * dz + dw * dw;
#pragma unroll
        for (int o = 16; o > 0; o >>= 1)
            s2 += __shfl_xor_sync(0xffffffffu, s2, o);
        float r = rsqrtf(s2 * (1.0f / 128.0f) + 1e-5f);
        float4 g4  = ((const float4*)gamma)[lane];
        float4 be4 = ((const float4*)beta)[lane];
        acc.x = dx * r * g4.x + be4.x;
        acc.y = dy * r * g4.y + be4.y;
        acc.z = dz * r * g4.z + be4.z;
        acc.w = dw * r * g4.w + be4.w;
        ((float4*)outp)[w * 32 + lane] = acc;
    } else {
        ((float4*)g_G)[w * 32 + lane] = acc;
    }
}

// ---------------- launch ------------------------------------------------------
extern "C" void kernel_launch(void* const* d_in, const int* in_sizes, int n_in,
                              void* d_out, int out_size) {
    const float* x   = (const float*)d_in[0];
    const void*  ei  = d_in[1];
    const float* ea  = (const float*)d_in[2];
    const float* W1  = (const float*)d_in[3];
    const float* b1  = (const float*)d_in[4];
    const float* W2  = (const float*)d_in[5];
    const float* b2  = (const float*)d_in[6];
    const float* lng = (const float*)d_in[7];
    const float* lnb = (const float*)d_in[8];

    int n = in_sizes[0] / D;   // 40000
    int e = in_sizes[2];       // 640000

    int nb = (n + 255) / 256;
    int eb = (e + 255) / 256;

    k_init<<<nb, 256>>>(ei, n);
    k_deg<<<eb, 256>>>(ei, ea, e);
    k_scan<<<1, 1024>>>(n);
    k_fill<<<eb, 256>>>(ei, ea, e);

    int gemm_blocks = (n + 127) / 128;
    int agg_blocks  = (n * 32 + 255) / 256;

    k_gemm<0><<<gemm_blocks, 256>>>(x, W1, n);
    k_agg<0><<<agg_blocks, 256>>>(b1, nullptr, nullptr, nullptr, n);
    k_gemm<1><<<gemm_blocks, 256>>>(nullptr, W2, n);
    k_agg<1><<<agg_blocks, 256>>>(b2, lng, lnb, (float*)d_out, n);
}

// round 11
// speedup vs baseline: 1.1716x; 1.1716x over previous
#include <cuda_runtime.h>

#define D 128
#define MAXN 40000
#define MAXE 640000

// ---------------- scratch (static device globals; no allocation) -------------
__device__ float g_deg[MAXN];
__device__ int   g_cnt[MAXN];
__device__ int   g_offs[MAXN + 1];
__device__ int   g_cursor[MAXN];
__device__ int   g_srcs[MAXE];
__device__ float g_nrm[MAXE];
__device__ __align__(16) float g_H[MAXN * D];   // h = X @ W (current layer)
__device__ __align__(16) float g_G[MAXN * D];   // post-agg activations
__device__ int   g_is64;                        // edge_index dtype flag

// ---------------- f32x2 packed-FMA helpers ------------------------------------
__device__ __forceinline__ unsigned long long pack2(float lo, float hi) {
    unsigned long long d;
    asm("mov.b64 %0, {%1, %2};" : "=l"(d) : "f"(lo), "f"(hi));
    return d;
}
__device__ __forceinline__ void unpack2(unsigned long long v, float& lo, float& hi) {
    asm("mov.b64 {%0, %1}, %2;" : "=f"(lo), "=f"(hi) : "l"(v));
}
__device__ __forceinline__ unsigned long long fma2(unsigned long long a,
                                                   unsigned long long b,
                                                   unsigned long long c) {
    unsigned long long d;
    asm("fma.rn.f32x2 %0, %1, %2, %3;" : "=l"(d) : "l"(a), "l"(b), "l"(c));
    return d;
}

// ---------------- init + dtype probe (R8 proven) -------------------------------
__global__ void k_init(const void* __restrict__ ei, int n) {
    int i = blockIdx.x * blockDim.x + threadIdx.x;
    if (i < n) { g_deg[i] = 1.0f; g_cnt[i] = 0; }   // 1.0 = self-loop weight
    if (blockIdx.x == 0) {
        const long long* p = (const long long*)ei;
        bool bad = false;
        for (int j = threadIdx.x; j < 1024; j += blockDim.x) {
            long long v = p[j];
            if (v < 0 || v >= MAXN) bad = true;
        }
        bad = __syncthreads_or(bad);
        if (threadIdx.x == 0) g_is64 = bad ? 0 : 1;
    }
}

__device__ __forceinline__ int edge_at(const void* ei, long long idx) {
    if (g_is64) return (int)((const long long*)ei)[idx];
    return ((const int*)ei)[idx];
}

__global__ void k_deg(const void* __restrict__ ei,
                      const float* __restrict__ ea, int e) {
    int i = blockIdx.x * blockDim.x + threadIdx.x;
    if (i < e) {
        int dst = edge_at(ei, (long long)e + i);
        atomicAdd(&g_deg[dst], ea[i]);
        atomicAdd(&g_cnt[dst], 1);
    }
}

// Single-block exclusive scan of g_cnt -> g_offs / g_cursor (n <= 40960)
__global__ void k_scan(int n) {
    __shared__ int s[1024];
    int t = threadIdx.x;
    int ch = (n + 1023) >> 10;
    int base = t * ch;
    int sum = 0;
    for (int j = 0; j < ch; j++) {
        int idx = base + j;
        if (idx < n) sum += g_cnt[idx];
    }
    s[t] = sum;
    __syncthreads();
    for (int off = 1; off < 1024; off <<= 1) {
        int v = (t >= off) ? s[t - off] : 0;
        __syncthreads();
        s[t] += v;
        __syncthreads();
    }
    if (t == 1023) g_offs[n] = s[1023];
    int prefix = (t == 0) ? 0 : s[t - 1];
    for (int j = 0; j < ch; j++) {
        int idx = base + j;
        if (idx < n) {
            g_offs[idx]   = prefix;
            g_cursor[idx] = prefix;
            prefix += g_cnt[idx];
        }
    }
}

__global__ void k_fill(const void* __restrict__ ei,
                       const float* __restrict__ ea, int e) {
    int i = blockIdx.x * blockDim.x + threadIdx.x;
    if (i < e) {
        int src = edge_at(ei, i);
        int dst = edge_at(ei, (long long)e + i);
        int pos = atomicAdd(&g_cursor[dst], 1);
        g_srcs[pos] = src;
        g_nrm[pos]  = rsqrtf(g_deg[src]) * ea[i] * rsqrtf(g_deg[dst]);
    }
}

// ---------------- SGEMM (f32x2, R8 shape + register-prefetch double buffer) --
// 256 threads, 128x128 tile, BK=16. Thread = 8 rows x 8 cols (rows packed
// pairwise -> fma.rn.f32x2). Next k-tile's LDGs issue before current tile's
// math; stores + one sync after compute. Shape (smem bytes per FMA) unchanged
// from R8 -- only the exposed global latency is removed.
template <int USE_G>
__global__ void __launch_bounds__(256) k_gemm(const float* __restrict__ Ain,
                                              const float* __restrict__ W,
                                              int nrows) {
    const float* __restrict__ A = USE_G ? (const float*)g_G : Ain;
    __shared__ float xs_t[2][16][130];   // [buf][k][row], stride 130
    __shared__ float ws[2][16][128];     // [buf][k][col]
    int tid = threadIdx.x;
    int tx = tid & 15;
    int ty = tid >> 4;
    int row0 = blockIdx.x * 128;

    // X load mapping: row = tid>>1, 8-wide k segment
    int lrow = tid >> 1;
    int lseg = (tid & 1) * 8;
    int grow = row0 + lrow;
    if (grow >= nrows) grow = nrows - 1;
    const float* aptr = &A[grow * D + lseg];

    // W load mapping: two rows (wr0, wr0+8), 4-wide col segment
    int wr0 = tid >> 6;              // 0..3
    int wc0 = (tid & 63) * 2;        // hmm -- use R8 mapping instead below
    // R8 mapping: 512 float4 over 256 threads, 2 each
    // j=0: i=tid,     r=i>>5 (0..7),  c4=(i&31)*4
    // j=1: i=tid+256, r=8..15,        c4 same
    int wrA = tid >> 5;              // 0..7
    int wcA = (tid & 31) * 4;
    (void)wr0; (void)wc0;

    unsigned long long acc[4][8];
#pragma unroll
    for (int m = 0; m < 4; m++)
#pragma unroll
        for (int nn = 0; nn < 8; nn++) acc[m][nn] = 0ull;

    // prologue: load k-tile 0 into buffer 0
    float4 xva = *(const float4*)aptr;
    float4 xvb = *(const float4*)(aptr + 4);
    float4 wv0 = *(const float4*)&W[wrA * D + wcA];
    float4 wv1 = *(const float4*)&W[(wrA + 8) * D + wcA];
    xs_t[0][lseg + 0][lrow] = xva.x; xs_t[0][lseg + 1][lrow] = xva.y;
    xs_t[0][lseg + 2][lrow] = xva.z; xs_t[0][lseg + 3][lrow] = xva.w;
    xs_t[0][lseg + 4][lrow] = xvb.x; xs_t[0][lseg + 5][lrow] = xvb.y;
    xs_t[0][lseg + 6][lrow] = xvb.z; xs_t[0][lseg + 7][lrow] = xvb.w;
    *(float4*)&ws[0][wrA][wcA]     = wv0;
    *(float4*)&ws[0][wrA + 8][wcA] = wv1;
    __syncthreads();

#pragma unroll
    for (int it = 0; it < 8; it++) {
        int cur = it & 1;
        int nxt = cur ^ 1;
        if (it < 7) {                        // prefetch next tile into registers
            int k0 = (it + 1) * 16;
            xva = *(const float4*)(aptr + k0);
            xvb = *(const float4*)(aptr + k0 + 4);
            wv0 = *(const float4*)&W[(k0 + wrA) * D + wcA];
            wv1 = *(const float4*)&W[(k0 + wrA + 8) * D + wcA];
        }
#pragma unroll
        for (int kk = 0; kk < 16; kk++) {
            unsigned long long rm2[4];
#pragma unroll
            for (int m = 0; m < 4; m++)
                rm2[m] = *(const unsigned long long*)&xs_t[cur][kk][ty * 8 + 2 * m];
            float4 fa = *(const float4*)&ws[cur][kk][tx * 8];
            float4 fb = *(const float4*)&ws[cur][kk][tx * 8 + 4];
            unsigned long long rnb[8];
            rnb[0] = pack2(fa.x, fa.x); rnb[1] = pack2(fa.y, fa.y);
            rnb[2] = pack2(fa.z, fa.z); rnb[3] = pack2(fa.w, fa.w);
            rnb[4] = pack2(fb.x, fb.x); rnb[5] = pack2(fb.y, fb.y);
            rnb[6] = pack2(fb.z, fb.z); rnb[7] = pack2(fb.w, fb.w);
#pragma unroll
            for (int m = 0; m < 4; m++)
#pragma unroll
                for (int nn = 0; nn < 8; nn++)
                    acc[m][nn] = fma2(rm2[m], rnb[nn], acc[m][nn]);
        }
        if (it < 7) {                        // commit prefetched tile, 1 sync
            xs_t[nxt][lseg + 0][lrow] = xva.x; xs_t[nxt][lseg + 1][lrow] = xva.y;
            xs_t[nxt][lseg + 2][lrow] = xva.z; xs_t[nxt][lseg + 3][lrow] = xva.w;
            xs_t[nxt][lseg + 4][lrow] = xvb.x; xs_t[nxt][lseg + 5][lrow] = xvb.y;
            xs_t[nxt][lseg + 6][lrow] = xvb.z; xs_t[nxt][lseg + 7][lrow] = xvb.w;
            *(float4*)&ws[nxt][wrA][wcA]     = wv0;
            *(float4*)&ws[nxt][wrA + 8][wcA] = wv1;
            __syncthreads();
        }
    }

#pragma unroll
    for (int m = 0; m < 4; m++) {
        float lo[8], hi[8];
#pragma unroll
        for (int nn = 0; nn < 8; nn++) unpack2(acc[m][nn], lo[nn], hi[nn]);
        int r_lo = row0 + ty * 8 + 2 * m;
        int r_hi = r_lo + 1;
        int c = tx * 8;
        if (r_lo < nrows) {
            *(float4*)&g_H[r_lo * D + c]     = make_float4(lo[0], lo[1], lo[2], lo[3]);
            *(float4*)&g_H[r_lo * D + c + 4] = make_float4(lo[4], lo[5], lo[6], lo[7]);
        }
        if (r_hi < nrows) {
            *(float4*)&g_H[r_hi * D + c]     = make_float4(hi[0], hi[1], hi[2], hi[3]);
            *(float4*)&g_H[r_hi * D + c + 4] = make_float4(hi[4], hi[5], hi[6], hi[7]);
        }
    }
}

// ---------------- aggregation: warp per node, float4 per lane (R8 proven) ----
template <int LN>
__global__ void k_agg(const float* __restrict__ bias,
                      const float* __restrict__ gamma, const float* __restrict__ beta,
                      float* __restrict__ outp, int n) {
    int w = (blockIdx.x * blockDim.x + threadIdx.x) >> 5;
    int lane = threadIdx.x & 31;
    if (w >= n) return;

    const float4* __restrict__ H4 = (const float4*)g_H;
    float di = rsqrtf(g_deg[w]);
    float selfw = di * di;
    float4 h = __ldg(&H4[w * 32 + lane]);
    float4 acc = make_float4(h.x * selfw, h.y * selfw, h.z * selfw, h.w * selfw);

    int ib = g_offs[w];
    int ie = g_offs[w + 1];
    int i = ib;
    for (; i + 4 <= ie; i += 4) {
        int   s0 = g_srcs[i],     s1 = g_srcs[i + 1];
        int   s2 = g_srcs[i + 2], s3 = g_srcs[i + 3];
        float w0 = g_nrm[i],      w1 = g_nrm[i + 1];
        float w2 = g_nrm[i + 2],  w3 = g_nrm[i + 3];
        float4 a = __ldg(&H4[s0 * 32 + lane]);
        float4 b = __ldg(&H4[s1 * 32 + lane]);
        float4 c = __ldg(&H4[s2 * 32 + lane]);
        float4 d = __ldg(&H4[s3 * 32 + lane]);
        acc.x += a.x * w0; acc.y += a.y * w0; acc.z += a.z * w0; acc.w += a.w * w0;
        acc.x += b.x * w1; acc.y += b.y * w1; acc.z += b.z * w1; acc.w += b.w * w1;
        acc.x += c.x * w2; acc.y += c.y * w2; acc.z += c.z * w2; acc.w += c.w * w2;
        acc.x += d.x * w3; acc.y += d.y * w3; acc.z += d.z * w3; acc.w += d.w * w3;
    }
    for (; i < ie; i++) {
        int s0 = g_srcs[i];
        float w0 = g_nrm[i];
        float4 a = __ldg(&H4[s0 * 32 + lane]);
        acc.x += a.x * w0; acc.y += a.y * w0; acc.z += a.z * w0; acc.w += a.w * w0;
    }

    float4 b4 = ((const float4*)bias)[lane];
    acc.x = fmaxf(acc.x + b4.x, 0.0f);
    acc.y = fmaxf(acc.y + b4.y, 0.0f);
    acc.z = fmaxf(acc.z + b4.z, 0.0f);
    acc.w = fmaxf(acc.w + b4.w, 0.0f);

    if (LN) {
        float s1 = acc.x + acc.y + acc.z + acc.w;
#pragma unroll
        for (int o = 16; o > 0; o >>= 1)
            s1 += __shfl_xor_sync(0xffffffffu, s1, o);
        float mu = s1 * (1.0f / 128.0f);
        float dx = acc.x - mu, dy = acc.y - mu, dz = acc.z - mu, dw = acc.w - mu;
        float s2 = dx * dx + dy * dy + dz * dz + dw * dw;
#pragma unroll
        for (int o = 16; o > 0; o >>= 1)
            s2 += __shfl_xor_sync(0xffffffffu, s2, o);
        float r = rsqrtf(s2 * (1.0f / 128.0f) + 1e-5f);
        float4 g4  = ((const float4*)gamma)[lane];
        float4 be4 = ((const float4*)beta)[lane];
        acc.x = dx * r * g4.x + be4.x;
        acc.y = dy * r * g4.y + be4.y;
        acc.z = dz * r * g4.z + be4.z;
        acc.w = dw * r * g4.w + be4.w;
        ((float4*)outp)[w * 32 + lane] = acc;
    } else {
        ((float4*)g_G)[w * 32 + lane] = acc;
    }
}

// ---------------- launch ------------------------------------------------------
extern "C" void kernel_launch(void* const* d_in, const int* in_sizes, int n_in,
                              void* d_out, int out_size) {
    const float* x   = (const float*)d_in[0];
    const void*  ei  = d_in[1];
    const float* ea  = (const float*)d_in[2];
    const float* W1  = (const float*)d_in[3];
    const float* b1  = (const float*)d_in[4];
    const float* W2  = (const float*)d_in[5];
    const float* b2  = (const float*)d_in[6];
    const float* lng = (const float*)d_in[7];
    const float* lnb = (const float*)d_in[8];

    int n = in_sizes[0] / D;   // 40000
    int e = in_sizes[2];       // 640000

    int nb = (n + 255) / 256;
    int eb = (e + 255) / 256;

    k_init<<<nb, 256>>>(ei, n);
    k_deg<<<eb, 256>>>(ei, ea, e);
    k_scan<<<1, 1024>>>(n);
    k_fill<<<eb, 256>>>(ei, ea, e);

    int gemm_blocks = (n + 127) / 128;
    int agg_blocks  = (n * 32 + 255) / 256;

    k_gemm<0><<<gemm_blocks, 256>>>(x, W1, n);
    k_agg<0><<<agg_blocks, 256>>>(b1, nullptr, nullptr, nullptr, n);
    k_gemm<1><<<gemm_blocks, 256>>>(nullptr, W2, n);
    k_agg<1><<<agg_blocks, 256>>>(b2, lng, lnb, (float*)d_out, n);
}

// round 12
// speedup vs baseline: 1.3760x; 1.1745x over previous
#include <cuda_runtime.h>

#define D 128
#define MAXN 40000
#define MAXE 640000

// ---------------- scratch (static device globals; no allocation) -------------
__device__ float g_deg[MAXN];
__device__ int   g_cnt[MAXN];
__device__ int   g_offs[MAXN + 1];
__device__ int   g_cursor[MAXN];
__device__ int   g_srcs[MAXE];
__device__ float g_nrm[MAXE];
__device__ __align__(16) float g_H[MAXN * D];   // h = X @ W (current layer)
__device__ __align__(16) float g_G[MAXN * D];   // post-agg activations
__device__ int   g_is64;                        // edge_index dtype flag

// ---------------- tf32 helpers -------------------------------------------------
__device__ __forceinline__ unsigned f2tf32(float x) {
    unsigned r;
    asm("cvt.rna.tf32.f32 %0, %1;" : "=r"(r) : "f"(x));
    return r;
}
__device__ __forceinline__ void mma_tf32(float* c, const unsigned* a,
                                         unsigned b0, unsigned b1) {
    asm volatile(
        "mma.sync.aligned.m16n8k8.row.col.f32.tf32.tf32.f32 "
        "{%0,%1,%2,%3}, {%4,%5,%6,%7}, {%8,%9}, {%0,%1,%2,%3};\n"
        : "+f"(c[0]), "+f"(c[1]), "+f"(c[2]), "+f"(c[3])
        : "r"(a[0]), "r"(a[1]), "r"(a[2]), "r"(a[3]), "r"(b0), "r"(b1));
}

// ---------------- init + dtype probe (R8 proven) -------------------------------
__global__ void k_init(const void* __restrict__ ei, int n) {
    int i = blockIdx.x * blockDim.x + threadIdx.x;
    if (i < n) { g_deg[i] = 1.0f; g_cnt[i] = 0; }   // 1.0 = self-loop weight
    if (blockIdx.x == 0) {
        const long long* p = (const long long*)ei;
        bool bad = false;
        for (int j = threadIdx.x; j < 1024; j += blockDim.x) {
            long long v = p[j];
            if (v < 0 || v >= MAXN) bad = true;
        }
        bad = __syncthreads_or(bad);
        if (threadIdx.x == 0) g_is64 = bad ? 0 : 1;
    }
}

__device__ __forceinline__ int edge_at(const void* ei, long long idx) {
    if (g_is64) return (int)((const long long*)ei)[idx];
    return ((const int*)ei)[idx];
}

__global__ void k_deg(const void* __restrict__ ei,
                      const float* __restrict__ ea, int e) {
    int i = blockIdx.x * blockDim.x + threadIdx.x;
    if (i < e) {
        int dst = edge_at(ei, (long long)e + i);
        atomicAdd(&g_deg[dst], ea[i]);
        atomicAdd(&g_cnt[dst], 1);
    }
}

// Single-block exclusive scan of g_cnt -> g_offs / g_cursor (n <= 40960)
__global__ void k_scan(int n) {
    __shared__ int s[1024];
    int t = threadIdx.x;
    int ch = (n + 1023) >> 10;
    int base = t * ch;
    int sum = 0;
    for (int j = 0; j < ch; j++) {
        int idx = base + j;
        if (idx < n) sum += g_cnt[idx];
    }
    s[t] = sum;
    __syncthreads();
    for (int off = 1; off < 1024; off <<= 1) {
        int v = (t >= off) ? s[t - off] : 0;
        __syncthreads();
        s[t] += v;
        __syncthreads();
    }
    if (t == 1023) g_offs[n] = s[1023];
    int prefix = (t == 0) ? 0 : s[t - 1];
    for (int j = 0; j < ch; j++) {
        int idx = base + j;
        if (idx < n) {
            g_offs[idx]   = prefix;
            g_cursor[idx] = prefix;
            prefix += g_cnt[idx];
        }
    }
}

__global__ void k_fill(const void* __restrict__ ei,
                       const float* __restrict__ ea, int e) {
    int i = blockIdx.x * blockDim.x + threadIdx.x;
    if (i < e) {
        int src = edge_at(ei, i);
        int dst = edge_at(ei, (long long)e + i);
        int pos = atomicAdd(&g_cursor[dst], 1);
        g_srcs[pos] = src;
        g_nrm[pos]  = rsqrtf(g_deg[src]) * ea[i] * rsqrtf(g_deg[dst]);
    }
}

// ---------------- tf32 tensor-core GEMM: g_H[n,128] = A[n,128] @ W[128,128] --
// 256 threads / 8 warps; block tile 128 rows x 128 cols. One smem pass converts
// W into m16n8k8 B-fragment layout (tf32). Each warp owns 16 rows: A fragments
// stream straight from global (L2-resident), double-buffered across k-steps;
// 16 nfrag x 16 kstep mma.sync into 64 fp32 acc regs. Single __syncthreads.
template <int USE_G>
__global__ void __launch_bounds__(256) k_gemm(const float* __restrict__ Ain,
                                              const float* __restrict__ W,
                                              int nrows) {
    const float* __restrict__ A = USE_G ? (const float*)g_G : Ain;
    extern __shared__ unsigned wf[];   // [ks16][nf16][lane32][2] tf32

    int tid = threadIdx.x;
    // W -> tf32 fragment layout. slot s = (ks*16 + nf)*32 + lane.
    for (int s = tid; s < 16 * 16 * 32; s += 256) {
        int lane = s & 31;
        int nf = (s >> 5) & 15;
        int ks = s >> 9;
        int k = ks * 8 + (lane & 3);
        int nn = nf * 8 + (lane >> 2);
        unsigned lo = f2tf32(W[k * D + nn]);
        unsigned hi = f2tf32(W[(k + 4) * D + nn]);
        *(uint2*)&wf[s * 2] = make_uint2(lo, hi);
    }
    __syncthreads();

    int wid = tid >> 5, lane = tid & 31;
    int ly = lane >> 2, lx = lane & 3;
    int rowbase = blockIdx.x * 128 + wid * 16;
    int ra = rowbase + ly;     if (ra >= nrows) ra = nrows - 1;
    int rb = rowbase + ly + 8; if (rb >= nrows) rb = nrows - 1;
    const float* pa = A + (size_t)ra * D + lx;
    const float* pb = A + (size_t)rb * D + lx;

    float acc[16][4];
#pragma unroll
    for (int nf = 0; nf < 16; nf++)
#pragma unroll
        for (int j = 0; j < 4; j++) acc[nf][j] = 0.0f;

    // A fragment double buffer (m16n8k8 row-major A layout)
    unsigned a_cur[4], a_nxt[4];
    a_cur[0] = f2tf32(pa[0]); a_cur[1] = f2tf32(pb[0]);
    a_cur[2] = f2tf32(pa[4]); a_cur[3] = f2tf32(pb[4]);

#pragma unroll
    for (int ks = 0; ks < 16; ks++) {
        if (ks < 15) {
            int k0 = (ks + 1) * 8;
            a_nxt[0] = f2tf32(pa[k0]);     a_nxt[1] = f2tf32(pb[k0]);
            a_nxt[2] = f2tf32(pa[k0 + 4]); a_nxt[3] = f2tf32(pb[k0 + 4]);
        }
        const unsigned* wrow = &wf[(ks * 16 * 32 + lane) * 2];
#pragma unroll
        for (int nf = 0; nf < 16; nf++) {
            uint2 b = *(const uint2*)&wrow[nf * 64];
            mma_tf32(acc[nf], a_cur, b.x, b.y);
        }
#pragma unroll
        for (int j = 0; j < 4; j++) a_cur[j] = a_nxt[j];
    }

    // epilogue: c0,c1 -> (row, 2*lx..+1); c2,c3 -> row+8
    int r1 = rowbase + ly;
    int r2 = rowbase + ly + 8;
#pragma unroll
    for (int nf = 0; nf < 16; nf++) {
        int c = nf * 8 + lx * 2;
        if (r1 < nrows)
            *(float2*)&g_H[(size_t)r1 * D + c] = make_float2(acc[nf][0], acc[nf][1]);
        if (r2 < nrows)
            *(float2*)&g_H[(size_t)r2 * D + c] = make_float2(acc[nf][2], acc[nf][3]);
    }
}

// ---------------- aggregation: warp per node, float4 per lane (R8 proven) ----
template <int LN>
__global__ void k_agg(const float* __restrict__ bias,
                      const float* __restrict__ gamma, const float* __restrict__ beta,
                      float* __restrict__ outp, int n) {
    int w = (blockIdx.x * blockDim.x + threadIdx.x) >> 5;
    int lane = threadIdx.x & 31;
    if (w >= n) return;

    const float4* __restrict__ H4 = (const float4*)g_H;
    float di = rsqrtf(g_deg[w]);
    float selfw = di * di;
    float4 h = __ldg(&H4[w * 32 + lane]);
    float4 acc = make_float4(h.x * selfw, h.y * selfw, h.z * selfw, h.w * selfw);

    int ib = g_offs[w];
    int ie = g_offs[w + 1];
    int i = ib;
    for (; i + 4 <= ie; i += 4) {
        int   s0 = g_srcs[i],     s1 = g_srcs[i + 1];
        int   s2 = g_srcs[i + 2], s3 = g_srcs[i + 3];
        float w0 = g_nrm[i],      w1 = g_nrm[i + 1];
        float w2 = g_nrm[i + 2],  w3 = g_nrm[i + 3];
        float4 a = __ldg(&H4[s0 * 32 + lane]);
        float4 b = __ldg(&H4[s1 * 32 + lane]);
        float4 c = __ldg(&H4[s2 * 32 + lane]);
        float4 d = __ldg(&H4[s3 * 32 + lane]);
        acc.x += a.x * w0; acc.y += a.y * w0; acc.z += a.z * w0; acc.w += a.w * w0;
        acc.x += b.x * w1; acc.y += b.y * w1; acc.z += b.z * w1; acc.w += b.w * w1;
        acc.x += c.x * w2; acc.y += c.y * w2; acc.z += c.z * w2; acc.w += c.w * w2;
        acc.x += d.x * w3; acc.y += d.y * w3; acc.z += d.z * w3; acc.w += d.w * w3;
    }
    for (; i < ie; i++) {
        int s0 = g_srcs[i];
        float w0 = g_nrm[i];
        float4 a = __ldg(&H4[s0 * 32 + lane]);
        acc.x += a.x * w0; acc.y += a.y * w0; acc.z += a.z * w0; acc.w += a.w * w0;
    }

    float4 b4 = ((const float4*)bias)[lane];
    acc.x = fmaxf(acc.x + b4.x, 0.0f);
    acc.y = fmaxf(acc.y + b4.y, 0.0f);
    acc.z = fmaxf(acc.z + b4.z, 0.0f);
    acc.w = fmaxf(acc.w + b4.w, 0.0f);

    if (LN) {
        float s1 = acc.x + acc.y + acc.z + acc.w;
#pragma unroll
        for (int o = 16; o > 0; o >>= 1)
            s1 += __shfl_xor_sync(0xffffffffu, s1, o);
        float mu = s1 * (1.0f / 128.0f);
        float dx = acc.x - mu, dy = acc.y - mu, dz = acc.z - mu, dw = acc.w - mu;
        float s2 = dx * dx + dy * dy + dz * dz + dw * dw;
#pragma unroll
        for (int o = 16; o > 0; o >>= 1)
            s2 += __shfl_xor_sync(0xffffffffu, s2, o);
        float r = rsqrtf(s2 * (1.0f / 128.0f) + 1e-5f);
        float4 g4  = ((const float4*)gamma)[lane];
        float4 be4 = ((const float4*)beta)[lane];
        acc.x = dx * r * g4.x + be4.x;
        acc.y = dy * r * g4.y + be4.y;
        acc.z = dz * r * g4.z + be4.z;
        acc.w = dw * r * g4.w + be4.w;
        ((float4*)outp)[w * 32 + lane] = acc;
    } else {
        ((float4*)g_G)[w * 32 + lane] = acc;
    }
}

// ---------------- launch ------------------------------------------------------
extern "C" void kernel_launch(void* const* d_in, const int* in_sizes, int n_in,
                              void* d_out, int out_size) {
    const float* x   = (const float*)d_in[0];
    const void*  ei  = d_in[1];
    const float* ea  = (const float*)d_in[2];
    const float* W1  = (const float*)d_in[3];
    const float* b1  = (const float*)d_in[4];
    const float* W2  = (const float*)d_in[5];
    const float* b2  = (const float*)d_in[6];
    const float* lng = (const float*)d_in[7];
    const float* lnb = (const float*)d_in[8];

    int n = in_sizes[0] / D;   // 40000
    int e = in_sizes[2];       // 640000

    int nb = (n + 255) / 256;
    int eb = (e + 255) / 256;

    const int WF_BYTES = 16 * 16 * 32 * 2 * 4;   // 64 KB dynamic smem
    cudaFuncSetAttribute(k_gemm<0>, cudaFuncAttributeMaxDynamicSharedMemorySize, WF_BYTES);
    cudaFuncSetAttribute(k_gemm<1>, cudaFuncAttributeMaxDynamicSharedMemorySize, WF_BYTES);

    k_init<<<nb, 256>>>(ei, n);
    k_deg<<<eb, 256>>>(ei, ea, e);
    k_scan<<<1, 1024>>>(n);
    k_fill<<<eb, 256>>>(ei, ea, e);

    int gemm_blocks = (n + 127) / 128;
    int agg_blocks  = (n * 32 + 255) / 256;

    k_gemm<0><<<gemm_blocks, 256, WF_BYTES>>>(x, W1, n);
    k_agg<0><<<agg_blocks, 256>>>(b1, nullptr, nullptr, nullptr, n);
    k_gemm<1><<<gemm_blocks, 256, WF_BYTES>>>(nullptr, W2, n);
    k_agg<1><<<agg_blocks, 256>>>(b2, lng, lnb, (float*)d_out, n);
}

// round 13
// speedup vs baseline: 1.4684x; 1.0671x over previous
#include <cuda_runtime.h>
#include <cuda_fp16.h>

#define D 128
#define MAXN 40000
#define MAXE 640000

// ---------------- scratch (static device globals; no allocation) -------------
__device__ float g_deg[MAXN];
__device__ int   g_cnt[MAXN];
__device__ int   g_offs[MAXN + 1];
__device__ int   g_cursor[MAXN];
__device__ __align__(16) int2   g_edge[MAXE];      // {src, nrm bits}
__device__ __align__(16) __half g_Hh[MAXN * D];    // h = A @ W, fp16 (gathered)
__device__ __align__(16) float  g_G[MAXN * D];     // post-agg activations (fp32)
__device__ int   g_is64;                           // edge_index dtype flag

// ---------------- tf32 helpers -------------------------------------------------
__device__ __forceinline__ unsigned f2tf32(float x) {
    unsigned r;
    asm("cvt.rna.tf32.f32 %0, %1;" : "=r"(r) : "f"(x));
    return r;
}
__device__ __forceinline__ void mma_tf32(float* c, const unsigned* a,
                                         unsigned b0, unsigned b1) {
    asm volatile(
        "mma.sync.aligned.m16n8k8.row.col.f32.tf32.tf32.f32 "
        "{%0,%1,%2,%3}, {%4,%5,%6,%7}, {%8,%9}, {%0,%1,%2,%3};\n"
        : "+f"(c[0]), "+f"(c[1]), "+f"(c[2]), "+f"(c[3])
        : "r"(a[0]), "r"(a[1]), "r"(a[2]), "r"(a[3]), "r"(b0), "r"(b1));
}

// ---------------- init + dtype probe (R8 proven) -------------------------------
__global__ void k_init(const void* __restrict__ ei, int n) {
    int i = blockIdx.x * blockDim.x + threadIdx.x;
    if (i < n) { g_deg[i] = 1.0f; g_cnt[i] = 0; }   // 1.0 = self-loop weight
    if (blockIdx.x == 0) {
        const long long* p = (const long long*)ei;
        bool bad = false;
        for (int j = threadIdx.x; j < 1024; j += blockDim.x) {
            long long v = p[j];
            if (v < 0 || v >= MAXN) bad = true;
        }
        bad = __syncthreads_or(bad);
        if (threadIdx.x == 0) g_is64 = bad ? 0 : 1;
    }
}

__device__ __forceinline__ int edge_at(const void* ei, long long idx) {
    if (g_is64) return (int)((const long long*)ei)[idx];
    return ((const int*)ei)[idx];
}

__global__ void k_deg(const void* __restrict__ ei,
                      const float* __restrict__ ea, int e) {
    int i = blockIdx.x * blockDim.x + threadIdx.x;
    if (i < e) {
        int dst = edge_at(ei, (long long)e + i);
        atomicAdd(&g_deg[dst], ea[i]);
        atomicAdd(&g_cnt[dst], 1);
    }
}

// Single-block exclusive scan of g_cnt -> g_offs / g_cursor (n <= 40960)
__global__ void k_scan(int n) {
    __shared__ int s[1024];
    int t = threadIdx.x;
    int ch = (n + 1023) >> 10;
    int base = t * ch;
    int sum = 0;
    for (int j = 0; j < ch; j++) {
        int idx = base + j;
        if (idx < n) sum += g_cnt[idx];
    }
    s[t] = sum;
    __syncthreads();
    for (int off = 1; off < 1024; off <<= 1) {
        int v = (t >= off) ? s[t - off] : 0;
        __syncthreads();
        s[t] += v;
        __syncthreads();
    }
    if (t == 1023) g_offs[n] = s[1023];
    int prefix = (t == 0) ? 0 : s[t - 1];
    for (int j = 0; j < ch; j++) {
        int idx = base + j;
        if (idx < n) {
            g_offs[idx]   = prefix;
            g_cursor[idx] = prefix;
            prefix += g_cnt[idx];
        }
    }
}

// int2-packed edge record: one scattered 8B store per edge (R10-proven piece)
__global__ void k_fill(const void* __restrict__ ei,
                       const float* __restrict__ ea, int e) {
    int i = blockIdx.x * blockDim.x + threadIdx.x;
    if (i < e) {
        int src = edge_at(ei, i);
        int dst = edge_at(ei, (long long)e + i);
        float nrm = rsqrtf(g_deg[src]) * ea[i] * rsqrtf(g_deg[dst]);
        int pos = atomicAdd(&g_cursor[dst], 1);
        g_edge[pos] = make_int2(src, __float_as_int(nrm));
    }
}

// ---------------- tf32 tensor-core GEMM: g_Hh[n,128] = A[n,128] @ W[128,128] -
// (R12 proven structure; epilogue now packs fp16.)
template <int USE_G>
__global__ void __launch_bounds__(256) k_gemm(const float* __restrict__ Ain,
                                              const float* __restrict__ W,
                                              int nrows) {
    const float* __restrict__ A = USE_G ? (const float*)g_G : Ain;
    extern __shared__ unsigned wf[];   // [ks16][nf16][lane32][2] tf32

    int tid = threadIdx.x;
    for (int s = tid; s < 16 * 16 * 32; s += 256) {
        int lane = s & 31;
        int nf = (s >> 5) & 15;
        int ks = s >> 9;
        int k = ks * 8 + (lane & 3);
        int nn = nf * 8 + (lane >> 2);
        unsigned lo = f2tf32(W[k * D + nn]);
        unsigned hi = f2tf32(W[(k + 4) * D + nn]);
        *(uint2*)&wf[s * 2] = make_uint2(lo, hi);
    }
    __syncthreads();

    int wid = tid >> 5, lane = tid & 31;
    int ly = lane >> 2, lx = lane & 3;
    int rowbase = blockIdx.x * 128 + wid * 16;
    int ra = rowbase + ly;     if (ra >= nrows) ra = nrows - 1;
    int rb = rowbase + ly + 8; if (rb >= nrows) rb = nrows - 1;
    const float* pa = A + (size_t)ra * D + lx;
    const float* pb = A + (size_t)rb * D + lx;

    float acc[16][4];
#pragma unroll
    for (int nf = 0; nf < 16; nf++)
#pragma unroll
        for (int j = 0; j < 4; j++) acc[nf][j] = 0.0f;

    unsigned a_cur[4], a_nxt[4];
    a_cur[0] = f2tf32(pa[0]); a_cur[1] = f2tf32(pb[0]);
    a_cur[2] = f2tf32(pa[4]); a_cur[3] = f2tf32(pb[4]);

#pragma unroll
    for (int ks = 0; ks < 16; ks++) {
        if (ks < 15) {
            int k0 = (ks + 1) * 8;
            a_nxt[0] = f2tf32(pa[k0]);     a_nxt[1] = f2tf32(pb[k0]);
            a_nxt[2] = f2tf32(pa[k0 + 4]); a_nxt[3] = f2tf32(pb[k0 + 4]);
        }
        const unsigned* wrow = &wf[(ks * 16 * 32 + lane) * 2];
#pragma unroll
        for (int nf = 0; nf < 16; nf++) {
            uint2 b = *(const uint2*)&wrow[nf * 64];
            mma_tf32(acc[nf], a_cur, b.x, b.y);
        }
#pragma unroll
        for (int j = 0; j < 4; j++) a_cur[j] = a_nxt[j];
    }

    // epilogue: pack pairs to half2. c0,c1 -> (r1, 2lx..+1); c2,c3 -> r2.
    int r1 = rowbase + ly;
    int r2 = rowbase + ly + 8;
#pragma unroll
    for (int nf = 0; nf < 16; nf++) {
        int c = nf * 8 + lx * 2;
        if (r1 < nrows)
            *(__half2*)&g_Hh[(size_t)r1 * D + c] = __floats2half2_rn(acc[nf][0], acc[nf][1]);
        if (r2 < nrows)
            *(__half2*)&g_Hh[(size_t)r2 * D + c] = __floats2half2_rn(acc[nf][2], acc[nf][3]);
    }
}

// ---------------- aggregation: warp per node, fp16 gather, 8-edge unroll -----
// out[n] = relu( sum_{e: dst=n} Hh[src_e]*nrm_e + Hh[n]/deg[n] + bias )
// Each lane owns 4 features (one uint2 = 4 halfs per row).
template <int LN>
__global__ void k_agg(const float* __restrict__ bias,
                      const float* __restrict__ gamma, const float* __restrict__ beta,
                      float* __restrict__ outp, int n) {
    int w = (blockIdx.x * blockDim.x + threadIdx.x) >> 5;
    int lane = threadIdx.x & 31;
    if (w >= n) return;

    const uint2* __restrict__ Hh = (const uint2*)g_Hh;   // 32 uint2 per row
    float di = rsqrtf(g_deg[w]);
    float selfw = di * di;

    uint2 vs = __ldg(&Hh[(size_t)w * 32 + lane]);
    float2 s0f = __half22float2(*(__half2*)&vs.x);
    float2 s1f = __half22float2(*(__half2*)&vs.y);
    float4 acc = make_float4(s0f.x * selfw, s0f.y * selfw,
                             s1f.x * selfw, s1f.y * selfw);

    int ib = g_offs[w];
    int ie = g_offs[w + 1];
    int i = ib;
    for (; i + 8 <= ie; i += 8) {
        int2 ed[8];
        uint2 v[8];
#pragma unroll
        for (int j = 0; j < 8; j++) ed[j] = g_edge[i + j];
#pragma unroll
        for (int j = 0; j < 8; j++)
            v[j] = __ldg(&Hh[(size_t)ed[j].x * 32 + lane]);
#pragma unroll
        for (int j = 0; j < 8; j++) {
            float wgt = __int_as_float(ed[j].y);
            float2 p0 = __half22float2(*(__half2*)&v[j].x);
            float2 p1 = __half22float2(*(__half2*)&v[j].y);
            acc.x += p0.x * wgt; acc.y += p0.y * wgt;
            acc.z += p1.x * wgt; acc.w += p1.y * wgt;
        }
    }
    for (; i < ie; i++) {
        int2 ed = g_edge[i];
        float wgt = __int_as_float(ed.y);
        uint2 v = __ldg(&Hh[(size_t)ed.x * 32 + lane]);
        float2 p0 = __half22float2(*(__half2*)&v.x);
        float2 p1 = __half22float2(*(__half2*)&v.y);
        acc.x += p0.x * wgt; acc.y += p0.y * wgt;
        acc.z += p1.x * wgt; acc.w += p1.y * wgt;
    }

    float4 b4 = ((const float4*)bias)[lane];
    acc.x = fmaxf(acc.x + b4.x, 0.0f);
    acc.y = fmaxf(acc.y + b4.y, 0.0f);
    acc.z = fmaxf(acc.z + b4.z, 0.0f);
    acc.w = fmaxf(acc.w + b4.w, 0.0f);

    if (LN) {
        float s1 = acc.x + acc.y + acc.z + acc.w;
#pragma unroll
        for (int o = 16; o > 0; o >>= 1)
            s1 += __shfl_xor_sync(0xffffffffu, s1, o);
        float mu = s1 * (1.0f / 128.0f);
        float dx = acc.x - mu, dy = acc.y - mu, dz = acc.z - mu, dw = acc.w - mu;
        float s2 = dx * dx + dy * dy + dz * dz + dw * dw;
#pragma unroll
        for (int o = 16; o > 0; o >>= 1)
            s2 += __shfl_xor_sync(0xffffffffu, s2, o);
        float r = rsqrtf(s2 * (1.0f / 128.0f) + 1e-5f);
        float4 g4  = ((const float4*)gamma)[lane];
        float4 be4 = ((const float4*)beta)[lane];
        acc.x = dx * r * g4.x + be4.x;
        acc.y = dy * r * g4.y + be4.y;
        acc.z = dz * r * g4.z + be4.z;
        acc.w = dw * r * g4.w + be4.w;
        ((float4*)outp)[w * 32 + lane] = acc;
    } else {
        ((float4*)g_G)[w * 32 + lane] = acc;
    }
}

// ---------------- launch ------------------------------------------------------
extern "C" void kernel_launch(void* const* d_in, const int* in_sizes, int n_in,
                              void* d_out, int out_size) {
    const float* x   = (const float*)d_in[0];
    const void*  ei  = d_in[1];
    const float* ea  = (const float*)d_in[2];
    const float* W1  = (const float*)d_in[3];
    const float* b1  = (const float*)d_in[4];
    const float* W2  = (const float*)d_in[5];
    const float* b2  = (const float*)d_in[6];
    const float* lng = (const float*)d_in[7];
    const float* lnb = (const float*)d_in[8];

    int n = in_sizes[0] / D;   // 40000
    int e = in_sizes[2];       // 640000

    int nb = (n + 255) / 256;
    int eb = (e + 255) / 256;

    const int WF_BYTES = 16 * 16 * 32 * 2 * 4;   // 64 KB dynamic smem
    cudaFuncSetAttribute(k_gemm<0>, cudaFuncAttributeMaxDynamicSharedMemorySize, WF_BYTES);
    cudaFuncSetAttribute(k_gemm<1>, cudaFuncAttributeMaxDynamicSharedMemorySize, WF_BYTES);

    k_init<<<nb, 256>>>(ei, n);
    k_deg<<<eb, 256>>>(ei, ea, e);
    k_scan<<<1, 1024>>>(n);
    k_fill<<<eb, 256>>>(ei, ea, e);

    int gemm_blocks = (n + 127) / 128;
    int agg_blocks  = (n * 32 + 255) / 256;

    k_gemm<0><<<gemm_blocks, 256, WF_BYTES>>>(x, W1, n);
    k_agg<0><<<agg_blocks, 256>>>(b1, nullptr, nullptr, nullptr, n);
    k_gemm<1><<<gemm_blocks, 256, WF_BYTES>>>(nullptr, W2, n);
    k_agg<1><<<agg_blocks, 256>>>(b2, lng, lnb, (float*)d_out, n);
}